// round 3
// baseline (speedup 1.0000x reference)
#include <cuda_runtime.h>
#include <cuda_bf16.h>

typedef __nv_bfloat16 bf16;

// Problem constants
#define HID   4096
#define TT    2048     // B*S tokens
#define SEQ   1024
#define BSZ   2
#define NH    32
#define NKV   8
#define HD    128

// ---------------- device-global scratch (no runtime allocation allowed) ----------------
__device__ __align__(128) bf16 g_Xhi[(size_t)TT * HID];
__device__ __align__(128) bf16 g_Xlo[(size_t)TT * HID];
__device__ __align__(128) bf16 g_Wq[(size_t)HID * HID];
__device__ __align__(128) bf16 g_Wk[(size_t)NKV * HD * HID];
__device__ __align__(128) bf16 g_Wv[(size_t)NKV * HD * HID];
__device__ __align__(128) bf16 g_Wo[(size_t)HID * HID];
__device__ __align__(128) bf16 g_Qhi[(size_t)BSZ * NH * SEQ * HD];
__device__ __align__(128) bf16 g_Qlo[(size_t)BSZ * NH * SEQ * HD];
__device__ __align__(128) bf16 g_Khi[(size_t)BSZ * NKV * SEQ * HD];
__device__ __align__(128) bf16 g_Klo[(size_t)BSZ * NKV * SEQ * HD];
__device__ __align__(128) bf16 g_Vhi[(size_t)BSZ * NKV * SEQ * HD];
__device__ __align__(128) bf16 g_Vlo[(size_t)BSZ * NKV * SEQ * HD];
__device__ __align__(128) bf16 g_AOhi[(size_t)TT * HID];
__device__ __align__(128) bf16 g_AOlo[(size_t)TT * HID];

// ---------------- small helpers ----------------
__device__ __forceinline__ void cp16(void* s, const void* g) {
    unsigned sa = (unsigned)__cvta_generic_to_shared(s);
    asm volatile("cp.async.cg.shared.global [%0], [%1], 16;" ::"r"(sa), "l"(g));
}
__device__ __forceinline__ void cp_commit() { asm volatile("cp.async.commit_group;"); }
__device__ __forceinline__ void cp_wait0() { asm volatile("cp.async.wait_group 0;"); }

__device__ __forceinline__ void ldsm4(unsigned addr, unsigned (&r)[4]) {
    asm volatile("ldmatrix.sync.aligned.m8n8.x4.shared.b16 {%0,%1,%2,%3}, [%4];"
                 : "=r"(r[0]), "=r"(r[1]), "=r"(r[2]), "=r"(r[3]) : "r"(addr));
}
__device__ __forceinline__ void ldsm4t(unsigned addr, unsigned (&r)[4]) {
    asm volatile("ldmatrix.sync.aligned.m8n8.x4.trans.shared.b16 {%0,%1,%2,%3}, [%4];"
                 : "=r"(r[0]), "=r"(r[1]), "=r"(r[2]), "=r"(r[3]) : "r"(addr));
}
__device__ __forceinline__ void mma_bf16(float (&c)[4], const unsigned (&a)[4], const unsigned* b) {
    asm volatile(
        "mma.sync.aligned.m16n8k16.row.col.f32.bf16.bf16.f32 "
        "{%0,%1,%2,%3}, {%4,%5,%6,%7}, {%8,%9}, {%0,%1,%2,%3};\n"
        : "+f"(c[0]), "+f"(c[1]), "+f"(c[2]), "+f"(c[3])
        : "r"(a[0]), "r"(a[1]), "r"(a[2]), "r"(a[3]), "r"(b[0]), "r"(b[1]));
}
// split two fp32 values into packed bf16 hi pair and lo (residual) pair
__device__ __forceinline__ void split2(float a, float b, unsigned& hi, unsigned& lo) {
    __nv_bfloat162 h = __floats2bfloat162_rn(a, b);
    float ha = __bfloat162float(h.x), hb = __bfloat162float(h.y);
    __nv_bfloat162 l = __floats2bfloat162_rn(a - ha, b - hb);
    hi = *reinterpret_cast<unsigned*>(&h);
    lo = *reinterpret_cast<unsigned*>(&l);
}
__device__ __forceinline__ void store_split(bf16* hi, bf16* lo, size_t idx, float v) {
    bf16 h = __float2bfloat16_rn(v);
    hi[idx] = h;
    lo[idx] = __float2bfloat16_rn(v - __bfloat162float(h));
}

// ---------------- conversion kernels ----------------
__global__ void i2bf_kernel(const int* __restrict__ w, bf16* __restrict__ o, int n) {
    int i = blockIdx.x * blockDim.x + threadIdx.x;
    if (i < n) o[i] = __float2bfloat16_rn((float)w[i]);
}
__global__ void split_f32_kernel(const float* __restrict__ x, bf16* __restrict__ hi,
                                 bf16* __restrict__ lo, int n) {
    int i = blockIdx.x * blockDim.x + threadIdx.x;
    if (i < n) {
        float v = x[i];
        bf16 h = __float2bfloat16_rn(v);
        hi[i] = h;
        lo[i] = __float2bfloat16_rn(v - __bfloat162float(h));
    }
}

// ---------------- split-bf16 GEMM: C[M,N] = (Ahi+Alo)[M,K=4096] * W[N,K]^T ----------------
// mode 0: fp32 token-major out (O projection). mode 1: split hi/lo write to [b,head,s,d].
#define BKT 32
#define KST 40                   // padded smem row stride (elements)
#define GT_E (128 * KST)         // elements per tile
#define GEMM_SMEM (2 * 3 * GT_E * 2)  // 61440 bytes

__global__ __launch_bounds__(256) void gemm_split(
    const bf16* __restrict__ Ahi, const bf16* __restrict__ Alo,
    const bf16* __restrict__ W,
    const float* __restrict__ scale, const float* __restrict__ bias,
    int N, int mode, int nheads,
    float* __restrict__ outF, bf16* __restrict__ outHi, bf16* __restrict__ outLo) {
    extern __shared__ bf16 sm[];
    const int tid = threadIdx.x, lane = tid & 31, wid = tid >> 5;
    const int mBase = blockIdx.y * 128, nBase = blockIdx.x * 128;
    const int wm = (wid & 3) * 32, wn = (wid >> 2) * 64;
    const unsigned sbase = (unsigned)__cvta_generic_to_shared(sm);

    float acc[2][8][4];
#pragma unroll
    for (int mi = 0; mi < 2; mi++)
#pragma unroll
        for (int nf = 0; nf < 8; nf++)
#pragma unroll
            for (int e = 0; e < 4; e++) acc[mi][nf][e] = 0.f;

    auto loadStage = [&](int st, int k0) {
        bf16* sAh = sm + (3 * st + 0) * GT_E;
        bf16* sAl = sm + (3 * st + 1) * GT_E;
        bf16* sB  = sm + (3 * st + 2) * GT_E;
#pragma unroll
        for (int i = 0; i < 2; i++) {
            int c = tid + i * 256;
            int row = c >> 2, cb = (c & 3) * 8;
            cp16(sAh + row * KST + cb, Ahi + (size_t)(mBase + row) * HID + k0 + cb);
            cp16(sAl + row * KST + cb, Alo + (size_t)(mBase + row) * HID + k0 + cb);
            cp16(sB  + row * KST + cb, W   + (size_t)(nBase + row) * HID + k0 + cb);
        }
    };

    loadStage(0, 0);
    cp_commit();
    const int KT = HID / BKT;  // 128
    for (int kt = 0; kt < KT; kt++) {
        cp_wait0();
        __syncthreads();
        if (kt + 1 < KT) { loadStage((kt + 1) & 1, (kt + 1) * BKT); cp_commit(); }
        int st = kt & 1;
        unsigned ahb = sbase + (3 * st + 0) * GT_E * 2;
        unsigned alb = sbase + (3 * st + 1) * GT_E * 2;
        unsigned bb  = sbase + (3 * st + 2) * GT_E * 2;
#pragma unroll
        for (int ks = 0; ks < 2; ks++) {
            int kc = ks * 16;
            unsigned ah[2][4], al[2][4], bF[4][4];
#pragma unroll
            for (int mi = 0; mi < 2; mi++) {
                int row = wm + mi * 16 + (lane & 15);
                int col = kc + (lane >> 4) * 8;
                ldsm4(ahb + (unsigned)(row * KST + col) * 2, ah[mi]);
                ldsm4(alb + (unsigned)(row * KST + col) * 2, al[mi]);
            }
#pragma unroll
            for (int ni = 0; ni < 4; ni++) {
                int row = wn + ni * 16 + (lane & 7) + ((lane >> 4) << 3);
                int col = kc + ((lane >> 3) & 1) * 8;
                ldsm4(bb + (unsigned)(row * KST + col) * 2, bF[ni]);
            }
#pragma unroll
            for (int mi = 0; mi < 2; mi++)
#pragma unroll
                for (int ni = 0; ni < 4; ni++) {
                    mma_bf16(acc[mi][2 * ni],     ah[mi], &bF[ni][0]);
                    mma_bf16(acc[mi][2 * ni + 1], ah[mi], &bF[ni][2]);
                    mma_bf16(acc[mi][2 * ni],     al[mi], &bF[ni][0]);
                    mma_bf16(acc[mi][2 * ni + 1], al[mi], &bF[ni][2]);
                }
        }
        __syncthreads();
    }

    // epilogue
#pragma unroll
    for (int mi = 0; mi < 2; mi++)
#pragma unroll
        for (int nf = 0; nf < 8; nf++)
#pragma unroll
            for (int e = 0; e < 4; e++) {
                int r = mBase + wm + mi * 16 + (lane >> 2) + ((e >> 1) << 3);
                int c = nBase + wn + nf * 8 + 2 * (lane & 3) + (e & 1);
                float v = acc[mi][nf][e] * scale[c];
                if (bias) v += bias[c];
                if (mode == 0) {
                    outF[(size_t)r * N + c] = v;
                } else {
                    int head = c >> 7, d = c & 127;
                    int b = r >> 10, s = r & 1023;
                    size_t dst = (((size_t)(b * nheads + head)) * SEQ + s) * HD + d;
                    store_split(outHi, outLo, dst, v);
                }
            }
}

// ---------------- flash attention (causal, GQA), split-bf16 3-term products ----------------
#define QST 136                        // padded row stride (elements) for 128-wide tiles
#define ATTN_SMEM (2 * 128 * QST * 2)  // 69632 bytes (Q stage == KV stage size)

__global__ __launch_bounds__(256) void attn_kernel(
    const bf16* __restrict__ Qhi, const bf16* __restrict__ Qlo,
    const bf16* __restrict__ Khi, const bf16* __restrict__ Klo,
    const bf16* __restrict__ Vhi, const bf16* __restrict__ Vlo,
    bf16* __restrict__ Ohi, bf16* __restrict__ Olo) {
    extern __shared__ bf16 sm[];
    const int tid = threadIdx.x, lane = tid & 31, wid = tid >> 5;
    const int qi = blockIdx.x, h = blockIdx.y, b = blockIdx.z;
    const int kvh = h >> 2;  // GROUPS = 4
    const unsigned sbase = (unsigned)__cvta_generic_to_shared(sm);
    const float SCALE = 0.08838834764831845f;  // 1/sqrt(128)
    const float LOG2E = 1.4426950408889634f;
    const int wm = wid * 16;

    // ---- stage Q tile (128x128 hi+lo) through smem into per-warp register fragments
    const size_t qoff = (((size_t)(b * NH + h)) * SEQ + qi * 128) * HD;
    {
        bf16* sQh = sm;
        bf16* sQl = sm + 128 * QST;
#pragma unroll
        for (int i = 0; i < 8; i++) {
            int c = tid + i * 256;
            int row = c >> 4, cb = (c & 15) * 8;
            cp16(sQh + row * QST + cb, Qhi + qoff + row * HD + cb);
            cp16(sQl + row * QST + cb, Qlo + qoff + row * HD + cb);
        }
        cp_commit();
        cp_wait0();
        __syncthreads();
    }
    unsigned qh[8][4], ql[8][4];
#pragma unroll
    for (int ks = 0; ks < 8; ks++) {
        int row = wm + (lane & 15);
        int col = ks * 16 + (lane >> 4) * 8;
        ldsm4(sbase + (unsigned)(row * QST + col) * 2, qh[ks]);
        ldsm4(sbase + (unsigned)(128 * QST + row * QST + col) * 2, ql[ks]);
    }
    __syncthreads();

    float o[16][4];
#pragma unroll
    for (int nf = 0; nf < 16; nf++)
#pragma unroll
        for (int e = 0; e < 4; e++) o[nf][e] = 0.f;
    float m0 = -1e30f, m1 = -1e30f, l0 = 0.f, l1 = 0.f;

    const int jn = 2 * qi + 2;  // causal: kv tiles of 64 up to diagonal
    for (int j = 0; j < jn; j++) {
        // ---- load K/V hi/lo tiles (64x128 each)
        const size_t koff = (((size_t)(b * NKV + kvh)) * SEQ + j * 64) * HD;
        bf16* sKh = sm;
        bf16* sKl = sm + 64 * QST;
        bf16* sVh = sm + 128 * QST;
        bf16* sVl = sm + 192 * QST;
#pragma unroll
        for (int i = 0; i < 4; i++) {
            int c = tid + i * 256;
            int row = c >> 4, cb = (c & 15) * 8;
            cp16(sKh + row * QST + cb, Khi + koff + row * HD + cb);
            cp16(sKl + row * QST + cb, Klo + koff + row * HD + cb);
            cp16(sVh + row * QST + cb, Vhi + koff + row * HD + cb);
            cp16(sVl + row * QST + cb, Vlo + koff + row * HD + cb);
        }
        cp_commit();
        cp_wait0();
        __syncthreads();

        // ---- scores S = Q.K^T (3 terms: QhKh + QlKh + QhKl)
        float s4[8][4];
#pragma unroll
        for (int nf = 0; nf < 8; nf++)
#pragma unroll
            for (int e = 0; e < 4; e++) s4[nf][e] = 0.f;
        unsigned khb = sbase;
        unsigned klb = sbase + (unsigned)(64 * QST) * 2;
#pragma unroll
        for (int ks = 0; ks < 8; ks++) {
            unsigned kf[4][4], lf[4][4];
#pragma unroll
            for (int ni = 0; ni < 4; ni++) {
                int row = ni * 16 + (lane & 7) + ((lane >> 4) << 3);
                int col = ks * 16 + ((lane >> 3) & 1) * 8;
                ldsm4(khb + (unsigned)(row * QST + col) * 2, kf[ni]);
                ldsm4(klb + (unsigned)(row * QST + col) * 2, lf[ni]);
            }
#pragma unroll
            for (int ni = 0; ni < 4; ni++) {
                mma_bf16(s4[2 * ni],     qh[ks], &kf[ni][0]);
                mma_bf16(s4[2 * ni + 1], qh[ks], &kf[ni][2]);
                mma_bf16(s4[2 * ni],     ql[ks], &kf[ni][0]);
                mma_bf16(s4[2 * ni + 1], ql[ks], &kf[ni][2]);
                mma_bf16(s4[2 * ni],     qh[ks], &lf[ni][0]);
                mma_bf16(s4[2 * ni + 1], qh[ks], &lf[ni][2]);
            }
        }

        // ---- scale + causal mask
        const int rbase = qi * 128 + wm + (lane >> 2);
        const bool needMask = (j >= 2 * qi);
#pragma unroll
        for (int nf = 0; nf < 8; nf++)
#pragma unroll
            for (int e = 0; e < 4; e++) {
                s4[nf][e] *= SCALE;
                if (needMask) {
                    int r = rbase + ((e >> 1) << 3);
                    int cg = j * 64 + nf * 8 + 2 * (lane & 3) + (e & 1);
                    if (cg > r) s4[nf][e] = -1e30f;
                }
            }

        // ---- online softmax (rows split: e<2 -> row0, e>=2 -> row1)
        float mx0 = -1e30f, mx1 = -1e30f;
#pragma unroll
        for (int nf = 0; nf < 8; nf++) {
            mx0 = fmaxf(mx0, fmaxf(s4[nf][0], s4[nf][1]));
            mx1 = fmaxf(mx1, fmaxf(s4[nf][2], s4[nf][3]));
        }
        mx0 = fmaxf(mx0, __shfl_xor_sync(0xffffffffu, mx0, 1));
        mx0 = fmaxf(mx0, __shfl_xor_sync(0xffffffffu, mx0, 2));
        mx1 = fmaxf(mx1, __shfl_xor_sync(0xffffffffu, mx1, 1));
        mx1 = fmaxf(mx1, __shfl_xor_sync(0xffffffffu, mx1, 2));
        float mn0 = fmaxf(m0, mx0), mn1 = fmaxf(m1, mx1);
        float c0 = exp2f((m0 - mn0) * LOG2E), c1 = exp2f((m1 - mn1) * LOG2E);
        m0 = mn0;
        m1 = mn1;
        float rs0 = 0.f, rs1 = 0.f;
#pragma unroll
        for (int nf = 0; nf < 8; nf++) {
            s4[nf][0] = exp2f((s4[nf][0] - mn0) * LOG2E);
            s4[nf][1] = exp2f((s4[nf][1] - mn0) * LOG2E);
            s4[nf][2] = exp2f((s4[nf][2] - mn1) * LOG2E);
            s4[nf][3] = exp2f((s4[nf][3] - mn1) * LOG2E);
            rs0 += s4[nf][0] + s4[nf][1];
            rs1 += s4[nf][2] + s4[nf][3];
        }
        rs0 += __shfl_xor_sync(0xffffffffu, rs0, 1);
        rs0 += __shfl_xor_sync(0xffffffffu, rs0, 2);
        rs1 += __shfl_xor_sync(0xffffffffu, rs1, 1);
        rs1 += __shfl_xor_sync(0xffffffffu, rs1, 2);
        l0 = l0 * c0 + rs0;
        l1 = l1 * c1 + rs1;
#pragma unroll
        for (int nf = 0; nf < 16; nf++) {
            o[nf][0] *= c0;
            o[nf][1] *= c0;
            o[nf][2] *= c1;
            o[nf][3] *= c1;
        }

        // ---- O += P.V (3 terms: PhVh + PhVl + PlVh)
        unsigned vhb = sbase + (unsigned)(128 * QST) * 2;
        unsigned vlb = sbase + (unsigned)(192 * QST) * 2;
#pragma unroll
        for (int kc = 0; kc < 4; kc++) {
            unsigned ph[4], pl[4];
            split2(s4[2 * kc][0],     s4[2 * kc][1],     ph[0], pl[0]);
            split2(s4[2 * kc][2],     s4[2 * kc][3],     ph[1], pl[1]);
            split2(s4[2 * kc + 1][0], s4[2 * kc + 1][1], ph[2], pl[2]);
            split2(s4[2 * kc + 1][2], s4[2 * kc + 1][3], ph[3], pl[3]);
#pragma unroll
            for (int dg = 0; dg < 8; dg++) {
                int row = kc * 16 + (lane & 15);
                int col = dg * 16 + (lane >> 4) * 8;
                unsigned vf[4], wf[4];
                ldsm4t(vhb + (unsigned)(row * QST + col) * 2, vf);
                ldsm4t(vlb + (unsigned)(row * QST + col) * 2, wf);
                mma_bf16(o[2 * dg],     ph, &vf[0]);
                mma_bf16(o[2 * dg + 1], ph, &vf[2]);
                mma_bf16(o[2 * dg],     ph, &wf[0]);
                mma_bf16(o[2 * dg + 1], ph, &wf[2]);
                mma_bf16(o[2 * dg],     pl, &vf[0]);
                mma_bf16(o[2 * dg + 1], pl, &vf[2]);
            }
        }
        __syncthreads();
    }

    // ---- epilogue: normalize, split, write token-major [tok][h*128+d]
    float inv0 = 1.f / l0, inv1 = 1.f / l1;
    const int tok0 = b * SEQ + qi * 128 + wm + (lane >> 2);
#pragma unroll
    for (int nf = 0; nf < 16; nf++)
#pragma unroll
        for (int e = 0; e < 4; e++) {
            int r = tok0 + ((e >> 1) << 3);
            int d = nf * 8 + 2 * (lane & 3) + (e & 1);
            float v = o[nf][e] * ((e >= 2) ? inv1 : inv0);
            store_split(Ohi, Olo, (size_t)r * HID + h * HD + d, v);
        }
}

// ---------------- host launch ----------------
extern "C" void kernel_launch(void* const* d_in, const int* in_sizes, int n_in,
                              void* d_out, int out_size) {
    (void)in_sizes; (void)n_in; (void)out_size;
    const float* hidden = (const float*)d_in[0];
    const int*   wq   = (const int*)d_in[2];
    const float* wq_s = (const float*)d_in[3];
    const float* bq   = (const float*)d_in[4];
    const int*   wk   = (const int*)d_in[5];
    const float* wk_s = (const float*)d_in[6];
    const float* bk   = (const float*)d_in[7];
    const int*   wv   = (const int*)d_in[8];
    const float* wv_s = (const float*)d_in[9];
    const int*   wo   = (const int*)d_in[10];
    const float* wo_s = (const float*)d_in[11];
    float* out = (float*)d_out;

    bf16 *Xhi, *Xlo, *Wq, *Wk, *Wv, *Wo, *Qh, *Ql, *Kh, *Kl, *Vh, *Vl, *AOh, *AOl;
    cudaGetSymbolAddress((void**)&Xhi, g_Xhi);
    cudaGetSymbolAddress((void**)&Xlo, g_Xlo);
    cudaGetSymbolAddress((void**)&Wq,  g_Wq);
    cudaGetSymbolAddress((void**)&Wk,  g_Wk);
    cudaGetSymbolAddress((void**)&Wv,  g_Wv);
    cudaGetSymbolAddress((void**)&Wo,  g_Wo);
    cudaGetSymbolAddress((void**)&Qh,  g_Qhi);
    cudaGetSymbolAddress((void**)&Ql,  g_Qlo);
    cudaGetSymbolAddress((void**)&Kh,  g_Khi);
    cudaGetSymbolAddress((void**)&Kl,  g_Klo);
    cudaGetSymbolAddress((void**)&Vh,  g_Vhi);
    cudaGetSymbolAddress((void**)&Vl,  g_Vlo);
    cudaGetSymbolAddress((void**)&AOh, g_AOhi);
    cudaGetSymbolAddress((void**)&AOl, g_AOlo);

    cudaFuncSetAttribute(gemm_split, cudaFuncAttributeMaxDynamicSharedMemorySize, GEMM_SMEM);
    cudaFuncSetAttribute(attn_kernel, cudaFuncAttributeMaxDynamicSharedMemorySize, ATTN_SMEM);

    // weights int32 -> bf16 (exact), hidden fp32 -> bf16 hi/lo split
    i2bf_kernel<<<(HID * HID + 255) / 256, 256>>>(wq, Wq, HID * HID);
    i2bf_kernel<<<(NKV * HD * HID + 255) / 256, 256>>>(wk, Wk, NKV * HD * HID);
    i2bf_kernel<<<(NKV * HD * HID + 255) / 256, 256>>>(wv, Wv, NKV * HD * HID);
    i2bf_kernel<<<(HID * HID + 255) / 256, 256>>>(wo, Wo, HID * HID);
    split_f32_kernel<<<(TT * HID + 255) / 256, 256>>>(hidden, Xhi, Xlo, TT * HID);

    // projections
    dim3 gq(HID / 128, TT / 128);        // (32,16)
    dim3 gkv(NKV * HD / 128, TT / 128);  // (8,16)
    gemm_split<<<gq, 256, GEMM_SMEM>>>(Xhi, Xlo, Wq, wq_s, bq, HID, 1, NH, nullptr, Qh, Ql);
    gemm_split<<<gkv, 256, GEMM_SMEM>>>(Xhi, Xlo, Wk, wk_s, bk, NKV * HD, 1, NKV, nullptr, Kh, Kl);
    gemm_split<<<gkv, 256, GEMM_SMEM>>>(Xhi, Xlo, Wv, wv_s, nullptr, NKV * HD, 1, NKV, nullptr, Vh, Vl);

    // causal GQA flash attention
    attn_kernel<<<dim3(SEQ / 128, NH, BSZ), 256, ATTN_SMEM>>>(Qh, Ql, Kh, Kl, Vh, Vl, AOh, AOl);

    // output projection -> fp32 d_out
    gemm_split<<<gq, 256, GEMM_SMEM>>>(AOh, AOl, Wo, wo_s, nullptr, HID, 0, 0, out, nullptr, nullptr);
}

// round 5
// speedup vs baseline: 1.0580x; 1.0580x over previous
#include <cuda_runtime.h>
#include <cuda_bf16.h>
#include <cstdint>

typedef __nv_bfloat16 bf16;

// Problem constants
#define HID   4096
#define TT    2048     // B*S tokens
#define SEQ   1024
#define BSZ   2
#define NH    32
#define NKV   8
#define HD    128

// ---------------- device-global scratch (no runtime allocation allowed) ----------------
__device__ __align__(128) bf16 g_Xhi[(size_t)TT * HID];
__device__ __align__(128) bf16 g_Xlo[(size_t)TT * HID];
__device__ __align__(128) bf16 g_Wq[(size_t)HID * HID];
__device__ __align__(128) bf16 g_Wk[(size_t)NKV * HD * HID];
__device__ __align__(128) bf16 g_Wv[(size_t)NKV * HD * HID];
__device__ __align__(128) bf16 g_Wo[(size_t)HID * HID];
__device__ __align__(128) bf16 g_Qhi[(size_t)BSZ * NH * SEQ * HD];
__device__ __align__(128) bf16 g_Qlo[(size_t)BSZ * NH * SEQ * HD];
__device__ __align__(128) bf16 g_Khi[(size_t)BSZ * NKV * SEQ * HD];
__device__ __align__(128) bf16 g_Klo[(size_t)BSZ * NKV * SEQ * HD];
__device__ __align__(128) bf16 g_Vhi[(size_t)BSZ * NKV * SEQ * HD];
__device__ __align__(128) bf16 g_Vlo[(size_t)BSZ * NKV * SEQ * HD];
__device__ __align__(128) bf16 g_AOhi[(size_t)TT * HID];
__device__ __align__(128) bf16 g_AOlo[(size_t)TT * HID];

// ---------------- helpers ----------------
__device__ __forceinline__ void cp16(void* s, const void* g) {
    unsigned sa = (unsigned)__cvta_generic_to_shared(s);
    asm volatile("cp.async.cg.shared.global [%0], [%1], 16;" ::"r"(sa), "l"(g));
}
__device__ __forceinline__ void cp_commit() { asm volatile("cp.async.commit_group;"); }
template <int N>
__device__ __forceinline__ void cp_waitg() { asm volatile("cp.async.wait_group %0;" ::"n"(N)); }

__device__ __forceinline__ void ldsm4(unsigned addr, unsigned (&r)[4]) {
    asm volatile("ldmatrix.sync.aligned.m8n8.x4.shared.b16 {%0,%1,%2,%3}, [%4];"
                 : "=r"(r[0]), "=r"(r[1]), "=r"(r[2]), "=r"(r[3]) : "r"(addr));
}
__device__ __forceinline__ void ldsm4t(unsigned addr, unsigned (&r)[4]) {
    asm volatile("ldmatrix.sync.aligned.m8n8.x4.trans.shared.b16 {%0,%1,%2,%3}, [%4];"
                 : "=r"(r[0]), "=r"(r[1]), "=r"(r[2]), "=r"(r[3]) : "r"(addr));
}
__device__ __forceinline__ void mma_bf16(float (&c)[4], const unsigned (&a)[4], const unsigned* b) {
    asm volatile(
        "mma.sync.aligned.m16n8k16.row.col.f32.bf16.bf16.f32 "
        "{%0,%1,%2,%3}, {%4,%5,%6,%7}, {%8,%9}, {%0,%1,%2,%3};\n"
        : "+f"(c[0]), "+f"(c[1]), "+f"(c[2]), "+f"(c[3])
        : "r"(a[0]), "r"(a[1]), "r"(a[2]), "r"(a[3]), "r"(b[0]), "r"(b[1]));
}
__device__ __forceinline__ void split2(float a, float b, unsigned& hi, unsigned& lo) {
    __nv_bfloat162 h = __floats2bfloat162_rn(a, b);
    float ha = __bfloat162float(h.x), hb = __bfloat162float(h.y);
    __nv_bfloat162 l = __floats2bfloat162_rn(a - ha, b - hb);
    hi = *reinterpret_cast<unsigned*>(&h);
    lo = *reinterpret_cast<unsigned*>(&l);
}
__device__ __forceinline__ void store_split(bf16* hi, bf16* lo, size_t idx, float v) {
    bf16 h = __float2bfloat16_rn(v);
    hi[idx] = h;
    lo[idx] = __float2bfloat16_rn(v - __bfloat162float(h));
}

// ---------------- vectorized conversion kernels ----------------
__global__ void i2bf8_kernel(const int* __restrict__ w, bf16* __restrict__ o, int n8) {
    int i = blockIdx.x * blockDim.x + threadIdx.x;
    if (i < n8) {
        const int4* wp = (const int4*)w;
        int4 a = wp[2 * i], b = wp[2 * i + 1];
        __nv_bfloat162 r0 = __floats2bfloat162_rn((float)a.x, (float)a.y);
        __nv_bfloat162 r1 = __floats2bfloat162_rn((float)a.z, (float)a.w);
        __nv_bfloat162 r2 = __floats2bfloat162_rn((float)b.x, (float)b.y);
        __nv_bfloat162 r3 = __floats2bfloat162_rn((float)b.z, (float)b.w);
        uint4 out;
        out.x = *reinterpret_cast<unsigned*>(&r0);
        out.y = *reinterpret_cast<unsigned*>(&r1);
        out.z = *reinterpret_cast<unsigned*>(&r2);
        out.w = *reinterpret_cast<unsigned*>(&r3);
        ((uint4*)o)[i] = out;
    }
}
__global__ void split8_kernel(const float* __restrict__ x, bf16* __restrict__ hi,
                              bf16* __restrict__ lo, int n8) {
    int i = blockIdx.x * blockDim.x + threadIdx.x;
    if (i < n8) {
        const float4* xp = (const float4*)x;
        float4 a = xp[2 * i], b = xp[2 * i + 1];
        float v[8] = {a.x, a.y, a.z, a.w, b.x, b.y, b.z, b.w};
        unsigned h[4], l[4];
#pragma unroll
        for (int j = 0; j < 4; j++) split2(v[2 * j], v[2 * j + 1], h[j], l[j]);
        ((uint4*)hi)[i] = make_uint4(h[0], h[1], h[2], h[3]);
        ((uint4*)lo)[i] = make_uint4(l[0], l[1], l[2], l[3]);
    }
}

// ---------------- split-bf16 GEMM: C[M,N] = (Ahi+Alo)[M,K=4096] * W[N,K]^T ----------------
// 128x128 CTA tile, BK=32, 3-stage cp.async pipeline, occupancy 2.
// mode 0: fp32 token-major out (O projection). mode 1: split hi/lo write to [b,head,s,d].
#define BKT 32
#define KST 40                    // padded smem row stride (elements): 80B rows, ldsm conflict-free
#define GROWS 384                 // 128 Ah + 128 Al + 128 B rows
#define STG_E (GROWS * KST)       // elements per stage
#define GEMM_SMEM (3 * STG_E * 2) // 92160 bytes

__global__ __launch_bounds__(256, 2) void gemm_split(
    const bf16* __restrict__ Ahi, const bf16* __restrict__ Alo,
    const bf16* __restrict__ W,
    const float* __restrict__ scale, const float* __restrict__ bias,
    int N, int mode, int nheads,
    float* __restrict__ outF, bf16* __restrict__ outHi, bf16* __restrict__ outLo) {
    extern __shared__ bf16 sm[];
    const int tid = threadIdx.x, lane = tid & 31, wid = tid >> 5;
    const int mBase = blockIdx.y * 128, nBase = blockIdx.x * 128;
    const int wm = (wid & 3) * 32, wn = (wid >> 2) * 64;
    const unsigned sbase = (unsigned)__cvta_generic_to_shared(sm);

    float acc[2][8][4];
#pragma unroll
    for (int mi = 0; mi < 2; mi++)
#pragma unroll
        for (int nf = 0; nf < 8; nf++)
#pragma unroll
            for (int e = 0; e < 4; e++) acc[mi][nf][e] = 0.f;

    auto loadStage = [&](int st, int k0) {
        bf16* s = sm + st * STG_E;
#pragma unroll
        for (int i = 0; i < 6; i++) {  // 1536 cp16 / 256 threads
            int idx = tid + i * 256;
            int row = idx >> 2, q = idx & 3;
            const bf16* src;
            if (row < 128)
                src = Ahi + (size_t)(mBase + row) * HID + k0 + q * 8;
            else if (row < 256)
                src = Alo + (size_t)(mBase + row - 128) * HID + k0 + q * 8;
            else
                src = W + (size_t)(nBase + row - 256) * HID + k0 + q * 8;
            cp16(s + row * KST + q * 8, src);
        }
    };

    loadStage(0, 0); cp_commit();
    loadStage(1, BKT); cp_commit();

    const int KT = HID / BKT;  // 128
    for (int kt = 0; kt < KT; kt++) {
        if (kt + 1 < KT) cp_waitg<1>(); else cp_waitg<0>();
        __syncthreads();
        if (kt + 2 < KT) { loadStage((kt + 2) % 3, (kt + 2) * BKT); cp_commit(); }

        const int st = kt % 3;
        const unsigned ahb = sbase + (unsigned)(st * STG_E) * 2;
        const unsigned alb = ahb + (unsigned)(128 * KST) * 2;
        const unsigned bb  = ahb + (unsigned)(256 * KST) * 2;
#pragma unroll
        for (int ks = 0; ks < 2; ks++) {
            int kc = ks * 16;
            unsigned ah[2][4], al[2][4], bF[4][4];
#pragma unroll
            for (int mi = 0; mi < 2; mi++) {
                int row = wm + mi * 16 + (lane & 15);
                int col = kc + (lane >> 4) * 8;
                ldsm4(ahb + (unsigned)(row * KST + col) * 2, ah[mi]);
                ldsm4(alb + (unsigned)(row * KST + col) * 2, al[mi]);
            }
#pragma unroll
            for (int ni = 0; ni < 4; ni++) {
                int row = wn + ni * 16 + (lane & 7) + ((lane >> 4) << 3);
                int col = kc + ((lane >> 3) & 1) * 8;
                ldsm4(bb + (unsigned)(row * KST + col) * 2, bF[ni]);
            }
#pragma unroll
            for (int mi = 0; mi < 2; mi++)
#pragma unroll
                for (int ni = 0; ni < 4; ni++) {
                    mma_bf16(acc[mi][2 * ni],     ah[mi], &bF[ni][0]);
                    mma_bf16(acc[mi][2 * ni + 1], ah[mi], &bF[ni][2]);
                    mma_bf16(acc[mi][2 * ni],     al[mi], &bF[ni][0]);
                    mma_bf16(acc[mi][2 * ni + 1], al[mi], &bF[ni][2]);
                }
        }
        // no trailing sync: next iteration's top sync protects slot reuse
    }

    // epilogue
#pragma unroll
    for (int mi = 0; mi < 2; mi++)
#pragma unroll
        for (int nf = 0; nf < 8; nf++)
#pragma unroll
            for (int e = 0; e < 4; e++) {
                int r = mBase + wm + mi * 16 + (lane >> 2) + ((e >> 1) << 3);
                int c = nBase + wn + nf * 8 + 2 * (lane & 3) + (e & 1);
                float v = acc[mi][nf][e] * scale[c];
                if (bias) v += bias[c];
                if (mode == 0) {
                    outF[(size_t)r * N + c] = v;
                } else {
                    int head = c >> 7, d = c & 127;
                    int b = r >> 10, s = r & 1023;
                    size_t dst = (((size_t)(b * nheads + head)) * SEQ + s) * HD + d;
                    store_split(outHi, outLo, dst, v);
                }
            }
}

// ---------------- flash attention (causal, GQA), split-bf16 3-term products ----------------
// 3-stage KV pipeline: stage = Kh|Kl|Vh|Vl, 64 rows each (256 rows x QST)
#define QST 136
#define ASTG_E (256 * QST)            // 34816 elements = 69632 B per stage
#define ATTN_SMEM (3 * ASTG_E * 2)    // 208896 bytes

__global__ __launch_bounds__(256) void attn_kernel(
    const bf16* __restrict__ Qhi, const bf16* __restrict__ Qlo,
    const bf16* __restrict__ Khi, const bf16* __restrict__ Klo,
    const bf16* __restrict__ Vhi, const bf16* __restrict__ Vlo,
    bf16* __restrict__ Ohi, bf16* __restrict__ Olo) {
    extern __shared__ bf16 sm[];
    const int tid = threadIdx.x, lane = tid & 31, wid = tid >> 5;
    const int qi = blockIdx.x, h = blockIdx.y, b = blockIdx.z;
    const int kvh = h >> 2;  // GROUPS = 4
    const unsigned sbase = (unsigned)__cvta_generic_to_shared(sm);
    const float SCALE = 0.08838834764831845f;  // 1/sqrt(128)
    const float LOG2E = 1.4426950408889634f;
    const int wm = wid * 16;

    // ---- stage Q tile (128x128 hi+lo) through smem slot 0 into register fragments
    const size_t qoff = (((size_t)(b * NH + h)) * SEQ + qi * 128) * HD;
    {
        bf16* sQh = sm;
        bf16* sQl = sm + 128 * QST;
#pragma unroll
        for (int i = 0; i < 8; i++) {
            int c = tid + i * 256;
            int row = c >> 4, cb = (c & 15) * 8;
            cp16(sQh + row * QST + cb, Qhi + qoff + row * HD + cb);
            cp16(sQl + row * QST + cb, Qlo + qoff + row * HD + cb);
        }
        cp_commit();
        cp_waitg<0>();
        __syncthreads();
    }
    unsigned qh[8][4], ql[8][4];
#pragma unroll
    for (int ks = 0; ks < 8; ks++) {
        int row = wm + (lane & 15);
        int col = ks * 16 + (lane >> 4) * 8;
        ldsm4(sbase + (unsigned)(row * QST + col) * 2, qh[ks]);
        ldsm4(sbase + (unsigned)(128 * QST + row * QST + col) * 2, ql[ks]);
    }
    __syncthreads();

    const size_t kvbase = ((size_t)(b * NKV + kvh)) * SEQ * HD;
    auto loadKV = [&](int slot, int j) {
        bf16* s = sm + slot * ASTG_E;
        const size_t koff = kvbase + (size_t)(j * 64) * HD;
#pragma unroll
        for (int i = 0; i < 16; i++) {
            int idx = tid + i * 256;
            int r = idx >> 4, q = (idx & 15) * 8;
            int reg = r >> 6, lr = r & 63;
            const bf16* src = (reg == 0 ? Khi : reg == 1 ? Klo : reg == 2 ? Vhi : Vlo)
                              + koff + (size_t)lr * HD + q;
            cp16(s + r * QST + q, src);
        }
    };

    float o[16][4];
#pragma unroll
    for (int nf = 0; nf < 16; nf++)
#pragma unroll
        for (int e = 0; e < 4; e++) o[nf][e] = 0.f;
    float m0 = -1e30f, m1 = -1e30f, l0 = 0.f, l1 = 0.f;

    const int jn = 2 * qi + 2;  // causal: kv tiles of 64 up to diagonal
    loadKV(0, 0); cp_commit();
    if (jn > 1) { loadKV(1, 1); cp_commit(); }

    for (int j = 0; j < jn; j++) {
        if (j + 1 < jn) cp_waitg<1>(); else cp_waitg<0>();
        __syncthreads();
        if (j + 2 < jn) { loadKV((j + 2) % 3, j + 2); cp_commit(); }

        const unsigned sb = sbase + (unsigned)((j % 3) * ASTG_E) * 2;
        const unsigned khb = sb;
        const unsigned klb = sb + (unsigned)(64 * QST) * 2;
        const unsigned vhb = sb + (unsigned)(128 * QST) * 2;
        const unsigned vlb = sb + (unsigned)(192 * QST) * 2;

        // ---- scores S = Q.K^T (3 terms: QhKh + QlKh + QhKl)
        float s4[8][4];
#pragma unroll
        for (int nf = 0; nf < 8; nf++)
#pragma unroll
            for (int e = 0; e < 4; e++) s4[nf][e] = 0.f;
#pragma unroll
        for (int ks = 0; ks < 8; ks++) {
            unsigned kf[4][4], lf[4][4];
#pragma unroll
            for (int ni = 0; ni < 4; ni++) {
                int row = ni * 16 + (lane & 7) + ((lane >> 4) << 3);
                int col = ks * 16 + ((lane >> 3) & 1) * 8;
                ldsm4(khb + (unsigned)(row * QST + col) * 2, kf[ni]);
                ldsm4(klb + (unsigned)(row * QST + col) * 2, lf[ni]);
            }
#pragma unroll
            for (int ni = 0; ni < 4; ni++) {
                mma_bf16(s4[2 * ni],     qh[ks], &kf[ni][0]);
                mma_bf16(s4[2 * ni + 1], qh[ks], &kf[ni][2]);
                mma_bf16(s4[2 * ni],     ql[ks], &kf[ni][0]);
                mma_bf16(s4[2 * ni + 1], ql[ks], &kf[ni][2]);
                mma_bf16(s4[2 * ni],     qh[ks], &lf[ni][0]);
                mma_bf16(s4[2 * ni + 1], qh[ks], &lf[ni][2]);
            }
        }

        // ---- scale + causal mask
        const int rbase = qi * 128 + wm + (lane >> 2);
        const bool needMask = (j >= 2 * qi);
#pragma unroll
        for (int nf = 0; nf < 8; nf++)
#pragma unroll
            for (int e = 0; e < 4; e++) {
                s4[nf][e] *= SCALE;
                if (needMask) {
                    int r = rbase + ((e >> 1) << 3);
                    int cg = j * 64 + nf * 8 + 2 * (lane & 3) + (e & 1);
                    if (cg > r) s4[nf][e] = -1e30f;
                }
            }

        // ---- online softmax (e<2 -> row0, e>=2 -> row1)
        float mx0 = -1e30f, mx1 = -1e30f;
#pragma unroll
        for (int nf = 0; nf < 8; nf++) {
            mx0 = fmaxf(mx0, fmaxf(s4[nf][0], s4[nf][1]));
            mx1 = fmaxf(mx1, fmaxf(s4[nf][2], s4[nf][3]));
        }
        mx0 = fmaxf(mx0, __shfl_xor_sync(0xffffffffu, mx0, 1));
        mx0 = fmaxf(mx0, __shfl_xor_sync(0xffffffffu, mx0, 2));
        mx1 = fmaxf(mx1, __shfl_xor_sync(0xffffffffu, mx1, 1));
        mx1 = fmaxf(mx1, __shfl_xor_sync(0xffffffffu, mx1, 2));
        float mn0 = fmaxf(m0, mx0), mn1 = fmaxf(m1, mx1);
        float c0 = exp2f((m0 - mn0) * LOG2E), c1 = exp2f((m1 - mn1) * LOG2E);
        m0 = mn0;
        m1 = mn1;
        float rs0 = 0.f, rs1 = 0.f;
#pragma unroll
        for (int nf = 0; nf < 8; nf++) {
            s4[nf][0] = exp2f((s4[nf][0] - mn0) * LOG2E);
            s4[nf][1] = exp2f((s4[nf][1] - mn0) * LOG2E);
            s4[nf][2] = exp2f((s4[nf][2] - mn1) * LOG2E);
            s4[nf][3] = exp2f((s4[nf][3] - mn1) * LOG2E);
            rs0 += s4[nf][0] + s4[nf][1];
            rs1 += s4[nf][2] + s4[nf][3];
        }
        rs0 += __shfl_xor_sync(0xffffffffu, rs0, 1);
        rs0 += __shfl_xor_sync(0xffffffffu, rs0, 2);
        rs1 += __shfl_xor_sync(0xffffffffu, rs1, 1);
        rs1 += __shfl_xor_sync(0xffffffffu, rs1, 2);
        l0 = l0 * c0 + rs0;
        l1 = l1 * c1 + rs1;
#pragma unroll
        for (int nf = 0; nf < 16; nf++) {
            o[nf][0] *= c0;
            o[nf][1] *= c0;
            o[nf][2] *= c1;
            o[nf][3] *= c1;
        }

        // ---- O += P.V (3 terms: PhVh + PhVl + PlVh)
#pragma unroll
        for (int kc = 0; kc < 4; kc++) {
            unsigned ph[4], pl[4];
            split2(s4[2 * kc][0],     s4[2 * kc][1],     ph[0], pl[0]);
            split2(s4[2 * kc][2],     s4[2 * kc][3],     ph[1], pl[1]);
            split2(s4[2 * kc + 1][0], s4[2 * kc + 1][1], ph[2], pl[2]);
            split2(s4[2 * kc + 1][2], s4[2 * kc + 1][3], ph[3], pl[3]);
#pragma unroll
            for (int dg = 0; dg < 8; dg++) {
                int row = kc * 16 + (lane & 15);
                int col = dg * 16 + (lane >> 4) * 8;
                unsigned vf[4], wf[4];
                ldsm4t(vhb + (unsigned)(row * QST + col) * 2, vf);
                ldsm4t(vlb + (unsigned)(row * QST + col) * 2, wf);
                mma_bf16(o[2 * dg],     ph, &vf[0]);
                mma_bf16(o[2 * dg + 1], ph, &vf[2]);
                mma_bf16(o[2 * dg],     ph, &wf[0]);
                mma_bf16(o[2 * dg + 1], ph, &wf[2]);
                mma_bf16(o[2 * dg],     pl, &vf[0]);
                mma_bf16(o[2 * dg + 1], pl, &vf[2]);
            }
        }
        // no trailing sync: next iteration's top sync protects slot reuse
    }

    // ---- epilogue: normalize, split, write token-major [tok][h*128+d]
    float inv0 = 1.f / l0, inv1 = 1.f / l1;
    const int tok0 = b * SEQ + qi * 128 + wm + (lane >> 2);
#pragma unroll
    for (int nf = 0; nf < 16; nf++)
#pragma unroll
        for (int e = 0; e < 4; e++) {
            int r = tok0 + ((e >> 1) << 3);
            int d = nf * 8 + 2 * (lane & 3) + (e & 1);
            float v = o[nf][e] * ((e >= 2) ? inv1 : inv0);
            store_split(Ohi, Olo, (size_t)r * HID + h * HD + d, v);
        }
}

// ---------------- host launch ----------------
extern "C" void kernel_launch(void* const* d_in, const int* in_sizes, int n_in,
                              void* d_out, int out_size) {
    (void)in_sizes; (void)n_in; (void)out_size;
    const float* hidden = (const float*)d_in[0];
    const int*   wq   = (const int*)d_in[2];
    const float* wq_s = (const float*)d_in[3];
    const float* bq   = (const float*)d_in[4];
    const int*   wk   = (const int*)d_in[5];
    const float* wk_s = (const float*)d_in[6];
    const float* bk   = (const float*)d_in[7];
    const int*   wv   = (const int*)d_in[8];
    const float* wv_s = (const float*)d_in[9];
    const int*   wo   = (const int*)d_in[10];
    const float* wo_s = (const float*)d_in[11];
    float* out = (float*)d_out;

    bf16 *Xhi, *Xlo, *Wq, *Wk, *Wv, *Wo, *Qh, *Ql, *Kh, *Kl, *Vh, *Vl, *AOh, *AOl;
    cudaGetSymbolAddress((void**)&Xhi, g_Xhi);
    cudaGetSymbolAddress((void**)&Xlo, g_Xlo);
    cudaGetSymbolAddress((void**)&Wq,  g_Wq);
    cudaGetSymbolAddress((void**)&Wk,  g_Wk);
    cudaGetSymbolAddress((void**)&Wv,  g_Wv);
    cudaGetSymbolAddress((void**)&Wo,  g_Wo);
    cudaGetSymbolAddress((void**)&Qh,  g_Qhi);
    cudaGetSymbolAddress((void**)&Ql,  g_Qlo);
    cudaGetSymbolAddress((void**)&Kh,  g_Khi);
    cudaGetSymbolAddress((void**)&Kl,  g_Klo);
    cudaGetSymbolAddress((void**)&Vh,  g_Vhi);
    cudaGetSymbolAddress((void**)&Vl,  g_Vlo);
    cudaGetSymbolAddress((void**)&AOh, g_AOhi);
    cudaGetSymbolAddress((void**)&AOl, g_AOlo);

    cudaFuncSetAttribute(gemm_split, cudaFuncAttributeMaxDynamicSharedMemorySize, GEMM_SMEM);
    cudaFuncSetAttribute(attn_kernel, cudaFuncAttributeMaxDynamicSharedMemorySize, ATTN_SMEM);

    // weights int32 -> bf16 (exact), hidden fp32 -> bf16 hi/lo split — vectorized x8
    i2bf8_kernel<<<(HID * HID / 8 + 255) / 256, 256>>>(wq, Wq, HID * HID / 8);
    i2bf8_kernel<<<(NKV * HD * HID / 8 + 255) / 256, 256>>>(wk, Wk, NKV * HD * HID / 8);
    i2bf8_kernel<<<(NKV * HD * HID / 8 + 255) / 256, 256>>>(wv, Wv, NKV * HD * HID / 8);
    i2bf8_kernel<<<(HID * HID / 8 + 255) / 256, 256>>>(wo, Wo, HID * HID / 8);
    split8_kernel<<<(TT * HID / 8 + 255) / 256, 256>>>(hidden, Xhi, Xlo, TT * HID / 8);

    // projections
    dim3 gq(HID / 128, TT / 128);        // (32,16)
    dim3 gkv(NKV * HD / 128, TT / 128);  // (8,16)
    gemm_split<<<gq, 256, GEMM_SMEM>>>(Xhi, Xlo, Wq, wq_s, bq, HID, 1, NH, nullptr, Qh, Ql);
    gemm_split<<<gkv, 256, GEMM_SMEM>>>(Xhi, Xlo, Wk, wk_s, bk, NKV * HD, 1, NKV, nullptr, Kh, Kl);
    gemm_split<<<gkv, 256, GEMM_SMEM>>>(Xhi, Xlo, Wv, wv_s, nullptr, NKV * HD, 1, NKV, nullptr, Vh, Vl);

    // causal GQA flash attention
    attn_kernel<<<dim3(SEQ / 128, NH, BSZ), 256, ATTN_SMEM>>>(Qh, Ql, Kh, Kl, Vh, Vl, AOh, AOl);

    // output projection -> fp32 d_out
    gemm_split<<<gq, 256, GEMM_SMEM>>>(AOh, AOl, Wo, wo_s, nullptr, HID, 0, 0, out, nullptr, nullptr);
}